// round 11
// baseline (speedup 1.0000x reference)
#include <cuda_runtime.h>
#include <cuda_bf16.h>
#include <math.h>

// ---------------- problem constants ----------------
#define BB   2048          // graphs
#define NP   68            // nodes per graph
#define NC   8             // clusters
#define FH   128           // hidden
#define NN   (BB*NP)       // 139264 nodes
#define EE   (BB*NP*8)     // 1114112 edges
#define CSZ  (NP*NP)       // 4624
#define MT   (NN/128)      // 1088 M-tiles of 128 rows

typedef unsigned long long ull;
typedef unsigned int uint32;

// ---------------- scratch (device globals: no allocation allowed) ----------------
__device__ float g_C [BB*CSZ];          // per-graph dst x src count matrix
__device__ float g_P [(size_t)NN*FH];   // H @ W_rel
__device__ float g_Rb[(size_t)NN*FH];   // H @ W_root + b
__device__ float g_HA[(size_t)NN*FH];
__device__ float g_HB[(size_t)NN*FH];
__device__ int   g_is64;
// [Wrel;Wroot]^T as bf16 hi/lo: 2 layers x 256 n-rows x 128 k, row-major k-contig
__device__ __align__(16) __nv_bfloat16 g_Bh16[2*256*128];
__device__ __align__(16) __nv_bfloat16 g_Bl16[2*256*128];

// ---------------- f32x2 packed helpers (conv path) ----------------
__device__ __forceinline__ void fma2(ull& d, ull a, ull b){
    asm("fma.rn.f32x2 %0, %1, %2, %0;" : "+l"(d) : "l"(a), "l"(b));
}
__device__ __forceinline__ ull dup2(float x){
    ull r; asm("mov.b64 %0, {%1, %1};" : "=l"(r) : "f"(x)); return r;
}
__device__ __forceinline__ float2 unpack2(ull v){
    float2 f; asm("mov.b64 {%0, %1}, %2;" : "=f"(f.x), "=f"(f.y) : "l"(v)); return f;
}

// ---------------- mma.sync helpers (base ISA, no 'a' features) ----------------
__device__ __forceinline__ uint32 smem_u32(const void* p){
    uint32 a; asm("{ .reg .u64 t; cvta.to.shared.u64 t, %1; cvt.u32.u64 %0, t; }" : "=r"(a) : "l"(p));
    return a;
}
__device__ __forceinline__ void ldm_x4(uint32* r, uint32 addr){
    asm volatile("ldmatrix.sync.aligned.m8n8.x4.shared.b16 {%0,%1,%2,%3}, [%4];"
        : "=r"(r[0]), "=r"(r[1]), "=r"(r[2]), "=r"(r[3]) : "r"(addr));
}
__device__ __forceinline__ void mma16816(float* c, const uint32* a, const uint32* b){
    asm volatile("mma.sync.aligned.m16n8k16.row.col.f32.bf16.bf16.f32 "
        "{%0,%1,%2,%3}, {%4,%5,%6,%7}, {%8,%9}, {%0,%1,%2,%3};"
        : "+f"(c[0]), "+f"(c[1]), "+f"(c[2]), "+f"(c[3])
        : "r"(a[0]), "r"(a[1]), "r"(a[2]), "r"(a[3]), "r"(b[0]), "r"(b[1]));
}

// ---------------- edge dtype detect ----------------
__global__ void k_detect(const int* __restrict__ ei){
    __shared__ int anynz;
    int t = threadIdx.x;
    if (t == 0) anynz = 0;
    __syncthreads();
    if (ei[2*t + 1] != 0) atomicOr(&anynz, 1);
    __syncthreads();
    if (t == 0) g_is64 = (anynz == 0) ? 1 : 0;
}

__global__ void k_zeroC(){
    size_t idx = (size_t)blockIdx.x*blockDim.x + threadIdx.x;
    size_t tot = (size_t)BB*CSZ;
    size_t str = (size_t)gridDim.x*blockDim.x;
    for (size_t i = idx; i < tot; i += str) g_C[i] = 0.0f;
}

__global__ void k_edges(const int* __restrict__ ei){
    const int is64 = g_is64;
    int e = blockIdx.x*blockDim.x + threadIdx.x;
    if (e >= EE) return;
    int s, d;
    if (is64){ s = ei[2*e]; d = ei[2*(EE + e)]; }
    else     { s = ei[e];   d = ei[EE + e];    }
    int gd = d / NP;  int ld = d - gd*NP;
    int gs = s / NP;  int ls = s - gs*NP;     // gs == gd by construction
    (void)gs;
    atomicAdd(&g_C[(size_t)gd*CSZ + ld*NP + ls], 1.0f);
}

// ---------------- W prep: [Wrel;Wroot]^T (n-major, k-contig) bf16 hi/lo ----------------
__global__ void k_prepB(const float* __restrict__ Wre2, const float* __restrict__ Wro2,
                        const float* __restrict__ Wre3, const float* __restrict__ Wro3){
    int idx = blockIdx.x*blockDim.x + threadIdx.x;  // 0..65535
    int layer = idx >> 15;
    int r = idx & 32767;
    int n = r >> 7, k = r & 127;
    const float* Wrel  = layer ? Wre3 : Wre2;
    const float* Wroot = layer ? Wro3 : Wro2;
    float w = (n < 128) ? Wrel[k*128 + n] : Wroot[k*128 + (n-128)];
    __nv_bfloat16 hi = __float2bfloat16(w);
    __nv_bfloat16 lo = __float2bfloat16(w - __bfloat162float(hi));
    g_Bh16[idx] = hi;
    g_Bl16[idx] = lo;
}

// ---------------- layer 1 (F_IN = 2) ----------------
__global__ void k_layer1(const float* __restrict__ x,
                         const float* __restrict__ Wrel, const float* __restrict__ Wroot,
                         const float* __restrict__ b){
    __shared__ float xs[NP*2], ax[NP*2], wr[2*FH], wo[2*FH], bs[FH];
    const int g = blockIdx.x, t = threadIdx.x;
    if (t < NP*2) xs[t] = x[(size_t)g*NP*2 + t];
    if (t < FH){
        wr[t] = Wrel[t];  wr[FH+t] = Wrel[FH+t];
        wo[t] = Wroot[t]; wo[FH+t] = Wroot[FH+t];
        bs[t] = b[t];
    }
    __syncthreads();
    if (t < NP*2){
        int n = t >> 1, d = t & 1;
        const float* crow = g_C + (size_t)g*CSZ + n*NP;
        float sv = 0.0f;
        for (int j = 0; j < NP; j++) sv += crow[j] * xs[j*2 + d];
        ax[t] = sv;
    }
    __syncthreads();
    for (int idx = t; idx < NP*FH; idx += blockDim.x){
        int n = idx >> 7, f = idx & 127;
        float v = ax[n*2]*wr[f] + ax[n*2+1]*wr[FH+f]
                + xs[n*2]*wo[f] + xs[n*2+1]*wo[FH+f] + bs[f];
        g_HA[(size_t)g*NP*FH + idx] = fmaxf(v, 0.0f);
    }
}

// ---------------- tensor-core dual GEMM via mma.sync ----------------
// smem rows padded to 272B (68 words): rows r..r+7 hit word-banks 0,4,...,28 -> conflict-free ldmatrix
#define BST       272
#define SB_BHI    0
#define SB_BLO    (256*BST)               // 69632
#define SB_AHI    (2*256*BST)             // 139264
#define SB_ALO    (2*256*BST + 128*BST)   // 174080
#define SB_BS     (2*256*BST + 2*128*BST) // 208896
#define GEMM_SMEM (SB_BS + 512)

__global__ void __launch_bounds__(512) k_gemm_mma(int layer, const float* __restrict__ bias){
    extern __shared__ unsigned char sm[];
    const uint32 smb = smem_u32(sm);
    const float* __restrict__ Hin = (layer == 2) ? g_HA : g_HB;
    const __nv_bfloat16* __restrict__ Bh = g_Bh16 + (layer-2)*32768;
    const __nv_bfloat16* __restrict__ Bl = g_Bl16 + (layer-2)*32768;
    const int t = threadIdx.x, w = t >> 5, lane = t & 31;
    const int wm = w & 3, wn = w >> 2;   // warp tile: rows wm*32..+32, cols wn*64..+64

    // stage B hi/lo into padded smem (once per CTA)
    for (int i = t; i < 256*16; i += 512){
        int row = i >> 4, kc = i & 15;
        *(uint4*)(sm + SB_BHI + row*BST + kc*16) = ((const uint4*)Bh)[i];
        *(uint4*)(sm + SB_BLO + row*BST + kc*16) = ((const uint4*)Bl)[i];
    }
    if (t < 128) ((float*)(sm + SB_BS))[t] = bias[t];
    __syncthreads();

    // per-thread ldmatrix offsets (byte offsets within A/B regions)
    uint32 arow[2], brow[4];
    #pragma unroll
    for (int mf = 0; mf < 2; mf++)
        arow[mf] = (wm*32 + mf*16 + (lane & 7) + ((lane >> 3) & 1)*8)*BST
                 + ((lane >> 4) & 1)*16;
    #pragma unroll
    for (int bq = 0; bq < 4; bq++)
        brow[bq] = (wn*64 + bq*16 + (lane & 7) + ((lane >> 4) & 1)*8)*BST
                 + ((lane >> 3) & 1)*16;

    const float* bsp = (const float*)(sm + SB_BS);

    for (int tile = blockIdx.x; tile < MT; tile += gridDim.x){
        // ---- load A tile (128x128 fp32), split -> bf16 hi/lo padded smem ----
        const float* Ht = Hin + (size_t)tile * 128 * 128;
        #pragma unroll
        for (int i = 0; i < 4; i++){
            int lin = i*512 + t;              // 0..2047 chunks of 8 k
            int row = lin >> 4, kc = (lin & 15) << 3;
            const float* src = Ht + row*128 + kc;
            float4 v0 = *(const float4*)(src);
            float4 v1 = *(const float4*)(src + 4);
            __nv_bfloat162 h0 = __floats2bfloat162_rn(v0.x, v0.y);
            __nv_bfloat162 h1 = __floats2bfloat162_rn(v0.z, v0.w);
            __nv_bfloat162 h2 = __floats2bfloat162_rn(v1.x, v1.y);
            __nv_bfloat162 h3 = __floats2bfloat162_rn(v1.z, v1.w);
            float2 f0 = __bfloat1622float2(h0), f1 = __bfloat1622float2(h1);
            float2 f2 = __bfloat1622float2(h2), f3 = __bfloat1622float2(h3);
            __nv_bfloat162 l0 = __floats2bfloat162_rn(v0.x - f0.x, v0.y - f0.y);
            __nv_bfloat162 l1 = __floats2bfloat162_rn(v0.z - f1.x, v0.w - f1.y);
            __nv_bfloat162 l2 = __floats2bfloat162_rn(v1.x - f2.x, v1.y - f2.y);
            __nv_bfloat162 l3 = __floats2bfloat162_rn(v1.z - f3.x, v1.w - f3.y);
            uint4 hp = make_uint4(*(uint32*)&h0, *(uint32*)&h1, *(uint32*)&h2, *(uint32*)&h3);
            uint4 lp = make_uint4(*(uint32*)&l0, *(uint32*)&l1, *(uint32*)&l2, *(uint32*)&l3);
            *(uint4*)(sm + SB_AHI + row*BST + kc*2) = hp;
            *(uint4*)(sm + SB_ALO + row*BST + kc*2) = lp;
        }
        __syncthreads();

        // ---- 3-term bf16 MMA: Ahi*Bhi + Alo*Bhi + Ahi*Blo ----
        float acc[2][8][4];
        #pragma unroll
        for (int mf = 0; mf < 2; mf++)
            #pragma unroll
            for (int nf = 0; nf < 8; nf++)
                #pragma unroll
                for (int q = 0; q < 4; q++) acc[mf][nf][q] = 0.0f;

        #pragma unroll
        for (int term = 0; term < 3; term++){
            const uint32 Ab = smb + ((term == 1) ? SB_ALO : SB_AHI);
            const uint32 Bb = smb + ((term == 2) ? SB_BLO : SB_BHI);
            #pragma unroll
            for (int ks = 0; ks < 8; ks++){
                const uint32 kb = ks*32;    // 16 k-elems * 2 bytes
                uint32 a[2][4];
                ldm_x4(a[0], Ab + arow[0] + kb);
                ldm_x4(a[1], Ab + arow[1] + kb);
                uint32 b[4][4];
                #pragma unroll
                for (int bq = 0; bq < 4; bq++) ldm_x4(b[bq], Bb + brow[bq] + kb);
                #pragma unroll
                for (int mf = 0; mf < 2; mf++)
                    #pragma unroll
                    for (int nf = 0; nf < 8; nf++)
                        mma16816(acc[mf][nf], a[mf], &b[nf >> 1][(nf & 1)*2]);
            }
        }

        // ---- epilogue: registers -> g_P / g_Rb (+bias) ----
        const int colw = wn*64 + (lane & 3)*2;
        #pragma unroll
        for (int mf = 0; mf < 2; mf++){
            const size_t row0 = (size_t)tile*128 + wm*32 + mf*16 + (lane >> 2);
            #pragma unroll
            for (int nf = 0; nf < 8; nf++){
                int col = colw + nf*8;
                if (col < 128){
                    *(float2*)(g_P + row0*128 + col)       = make_float2(acc[mf][nf][0], acc[mf][nf][1]);
                    *(float2*)(g_P + (row0+8)*128 + col)   = make_float2(acc[mf][nf][2], acc[mf][nf][3]);
                } else {
                    int c2 = col - 128;
                    float b0 = bsp[c2], b1 = bsp[c2+1];
                    *(float2*)(g_Rb + row0*128 + c2)     = make_float2(acc[mf][nf][0]+b0, acc[mf][nf][1]+b1);
                    *(float2*)(g_Rb + (row0+8)*128 + c2) = make_float2(acc[mf][nf][2]+b0, acc[mf][nf][3]+b1);
                }
            }
        }
        __syncthreads();   // all warps done with A smem before next tile overwrites
    }
}

// ---------------- conv-apply: H_out = relu(C_g @ P_g + Rb_g) ----------------
#define CONV_SMEM ((NP*FH + CSZ)*4)
__global__ void k_conv(int layer){
    extern __shared__ float smf[];
    float* Ps = smf;            // 68*128
    float* Cs = smf + NP*FH;    // 68*68
    const int g = blockIdx.x, t = threadIdx.x;
    float* __restrict__ Hout = (layer == 2) ? g_HB : g_HA;

    const float* Pg = g_P + (size_t)g*NP*FH;
    for (int i = t; i < NP*FH; i += 544) Ps[i] = Pg[i];
    const float* Cg = g_C + (size_t)g*CSZ;
    for (int i = t; i < CSZ; i += 544) Cs[i] = Cg[i];
    __syncthreads();

    const int n  = t >> 3;
    const int cg = t & 7;
    const float* rb = g_Rb + ((size_t)g*NP + n)*FH;
    ull acc[8];
    #pragma unroll
    for (int u = 0; u < 8; u++) acc[u] = *(const ull*)(rb + 2*(cg + 8*u));

    const float* crow = Cs + n*NP;
    #pragma unroll 4
    for (int j = 0; j < NP; j++){
        ull cc = dup2(crow[j]);
        const float* pr = Ps + j*FH;
        #pragma unroll
        for (int u = 0; u < 8; u++){
            ull pv = *(const ull*)(pr + 2*(cg + 8*u));
            fma2(acc[u], cc, pv);
        }
    }
    float* ho = Hout + ((size_t)g*NP + n)*FH;
    #pragma unroll
    for (int u = 0; u < 8; u++){
        float2 v = unpack2(acc[u]);
        v.x = fmaxf(v.x, 0.0f); v.y = fmaxf(v.y, 0.0f);
        *(float2*)(ho + 2*(cg + 8*u)) = v;
    }
}

// ---------------- pool: softmax(s) einsum, maxpool(1,8), fc ----------------
__global__ void k_pool(const float* __restrict__ s_in,
                       const float* __restrict__ fcw, const float* __restrict__ fcb,
                       float* __restrict__ out){
    __shared__ float ssm[NP*NC];
    __shared__ float xp[NC*FH];
    __shared__ float red[128];
    const int g = blockIdx.x, t = threadIdx.x;

    if (t < NP){
        float v[NC]; float m = -1e30f;
        #pragma unroll
        for (int k = 0; k < NC; k++){ v[k] = s_in[((size_t)g*NP + t)*NC + k]; m = fmaxf(m, v[k]); }
        float sum = 0.0f;
        #pragma unroll
        for (int k = 0; k < NC; k++){ v[k] = expf(v[k]-m); sum += v[k]; }
        float inv = 1.0f/sum;
        #pragma unroll
        for (int k = 0; k < NC; k++) ssm[t*NC+k] = v[k]*inv;
    }
    __syncthreads();

    const float* Hg = g_HA + (size_t)g*NP*FH;
    for (int idx = t; idx < NC*FH; idx += 256){
        int c = idx >> 7, f = idx & 127;
        float acc = 0.0f;
        for (int n = 0; n < NP; n++) acc += ssm[n*NC+c] * Hg[n*FH + f];
        xp[c*FH + f] = acc;
    }
    __syncthreads();

    if (t < 128){
        int c = t >> 4, j = t & 15;
        float m = xp[c*FH + j*8];
        #pragma unroll
        for (int u = 1; u < 8; u++) m = fmaxf(m, xp[c*FH + j*8 + u]);
        red[t] = m * fcw[t];
    }
    __syncthreads();
    if (t < 64) red[t] += red[t+64];
    __syncthreads();
    if (t < 32){
        float v = red[t] + red[t+32];
        #pragma unroll
        for (int o = 16; o; o >>= 1) v += __shfl_down_sync(0xffffffffu, v, o);
        if (t == 0) out[g] = v + fcb[0];
    }
}

// ---------------- launch ----------------
extern "C" void kernel_launch(void* const* d_in, const int* in_sizes, int n_in,
                              void* d_out, int out_size){
    const float* x    = (const float*)d_in[0];
    const int*   ei   = (const int*)  d_in[1];
    const float* s_in = (const float*)d_in[3];
    const float* Wro1 = (const float*)d_in[4];
    const float* Wre1 = (const float*)d_in[5];
    const float* b1   = (const float*)d_in[6];
    const float* Wro2 = (const float*)d_in[7];
    const float* Wre2 = (const float*)d_in[8];
    const float* b2   = (const float*)d_in[9];
    const float* Wro3 = (const float*)d_in[10];
    const float* Wre3 = (const float*)d_in[11];
    const float* b3   = (const float*)d_in[12];
    const float* fcw  = (const float*)d_in[13];
    const float* fcb  = (const float*)d_in[14];
    float* out = (float*)d_out;
    (void)in_sizes; (void)n_in; (void)out_size;

    cudaFuncSetAttribute(k_gemm_mma, cudaFuncAttributeMaxDynamicSharedMemorySize, GEMM_SMEM);
    cudaFuncSetAttribute(k_conv,     cudaFuncAttributeMaxDynamicSharedMemorySize, CONV_SMEM);

    k_detect<<<1, 256>>>(ei);
    k_zeroC<<<4096, 256>>>();
    k_edges<<<EE/256, 256>>>(ei);
    k_prepB<<<256, 256>>>(Wre2, Wro2, Wre3, Wro3);

    k_layer1<<<BB, 256>>>(x, Wre1, Wro1, b1);                 // -> g_HA

    k_gemm_mma<<<148, 512, GEMM_SMEM>>>(2, b2);               // g_HA -> g_P, g_Rb
    k_conv<<<BB, 544, CONV_SMEM>>>(2);                        // -> g_HB

    k_gemm_mma<<<148, 512, GEMM_SMEM>>>(3, b3);               // g_HB -> g_P, g_Rb
    k_conv<<<BB, 544, CONV_SMEM>>>(3);                        // -> g_HA

    k_pool<<<BB, 256>>>(s_in, fcw, fcb, out);
}

// round 12
// speedup vs baseline: 1.7485x; 1.7485x over previous
#include <cuda_runtime.h>
#include <math.h>

// ---------------- problem constants ----------------
#define BB   2048          // graphs
#define NP   68            // nodes per graph
#define NC   8             // clusters
#define FH   128           // hidden
#define NN   (BB*NP)       // 139264 nodes
#define EE   (BB*NP*8)     // 1114112 edges
#define EPG  (NP*8)        // 544 edges per graph
#define GT   (NN/64)       // 2176 GEMM M-tiles

typedef unsigned long long ull;

// ---------------- scratch (device globals: no allocation allowed) ----------------
__device__ float g_P [(size_t)NN*FH];   // H @ W_rel
__device__ float g_Rb[(size_t)NN*FH];   // H @ W_root + b
__device__ float g_HA[(size_t)NN*FH];
__device__ float g_HB[(size_t)NN*FH];
__device__ int   g_is64;
// CSR: per-node in-edge lists (local src ids)
__device__ int           g_cnt[NN];
__device__ int           g_off[NN];
__device__ int           g_cur[NN];
__device__ unsigned char g_srcs[EE];

// ---------------- f32x2 packed helpers ----------------
__device__ __forceinline__ void fma2(ull& d, ull a, ull b){
    asm("fma.rn.f32x2 %0, %1, %2, %0;" : "+l"(d) : "l"(a), "l"(b));
}
__device__ __forceinline__ ull dup2(float x){
    ull r; asm("mov.b64 %0, {%1, %1};" : "=l"(r) : "f"(x)); return r;
}
__device__ __forceinline__ float2 unpack2(ull v){
    float2 f; asm("mov.b64 {%0, %1}, %2;" : "=f"(f.x), "=f"(f.y) : "l"(v)); return f;
}

// ---------------- edge dtype detect: int64 has zero high words ----------------
__global__ void k_detect(const int* __restrict__ ei){
    __shared__ int anynz;
    int t = threadIdx.x;
    if (t == 0) anynz = 0;
    __syncthreads();
    if (ei[2*t + 1] != 0) atomicOr(&anynz, 1);
    __syncthreads();
    if (t == 0) g_is64 = (anynz == 0) ? 1 : 0;
}

__global__ void k_zcnt(){
    int i = blockIdx.x*blockDim.x + threadIdx.x;
    if (i < NN) g_cnt[i] = 0;
}

__global__ void k_count(const int* __restrict__ ei){
    const int is64 = g_is64;
    int e = blockIdx.x*blockDim.x + threadIdx.x;
    if (e >= EE) return;
    int d = is64 ? ei[2*(EE + e)] : ei[EE + e];
    atomicAdd(&g_cnt[d], 1);
}

// exclusive scan per graph (544 edges/graph -> base g*EPG)
__global__ void k_offs(){
    const int g = blockIdx.x;
    if (threadIdx.x != 0) return;
    int run = g * EPG;
    #pragma unroll 4
    for (int n = 0; n < NP; n++){
        int idx = g*NP + n;
        g_off[idx] = run;
        g_cur[idx] = run;
        run += g_cnt[idx];
    }
}

__global__ void k_scatter(const int* __restrict__ ei){
    const int is64 = g_is64;
    int e = blockIdx.x*blockDim.x + threadIdx.x;
    if (e >= EE) return;
    int s, d;
    if (is64){ s = ei[2*e]; d = ei[2*(EE + e)]; }
    else     { s = ei[e];   d = ei[EE + e];    }
    int gs = s / NP;  int ls = s - gs*NP;
    int pos = atomicAdd(&g_cur[d], 1);
    g_srcs[pos] = (unsigned char)ls;
}

// deterministic order: insertion-sort each node's src list
__global__ void k_sortsrc(){
    int n = blockIdx.x*blockDim.x + threadIdx.x;
    if (n >= NN) return;
    int off = g_off[n], c = g_cnt[n];
    for (int i = 1; i < c; i++){
        unsigned char key = g_srcs[off+i];
        int j = i - 1;
        while (j >= 0 && g_srcs[off+j] > key){ g_srcs[off+j+1] = g_srcs[off+j]; j--; }
        g_srcs[off+j+1] = key;
    }
}

// ---------------- layer 1 (F_IN = 2): HA = relu(agg@Wrel + x@Wroot + b) ----------------
__global__ void k_layer1(const float* __restrict__ x,
                         const float* __restrict__ Wrel, const float* __restrict__ Wroot,
                         const float* __restrict__ b){
    __shared__ float xs[NP*2], ax[NP*2], wr[2*FH], wo[2*FH], bs[FH];
    const int g = blockIdx.x, t = threadIdx.x;
    if (t < NP*2) xs[t] = x[(size_t)g*NP*2 + t];
    if (t < FH){
        wr[t] = Wrel[t];  wr[FH+t] = Wrel[FH+t];
        wo[t] = Wroot[t]; wo[FH+t] = Wroot[FH+t];
        bs[t] = b[t];
    }
    __syncthreads();
    if (t < NP*2){
        int n = t >> 1, d = t & 1;
        int off = g_off[g*NP + n], cnt = g_cnt[g*NP + n];
        float sv = 0.0f;
        for (int i = 0; i < cnt; i++) sv += xs[((int)g_srcs[off+i])*2 + d];
        ax[t] = sv;
    }
    __syncthreads();
    for (int idx = t; idx < NP*FH; idx += blockDim.x){
        int n = idx >> 7, f = idx & 127;
        float v = ax[n*2]*wr[f] + ax[n*2+1]*wr[FH+f]
                + xs[n*2]*wo[f] + xs[n*2+1]*wo[FH+f] + bs[f];
        g_HA[(size_t)g*NP*FH + idx] = fmaxf(v, 0.0f);
    }
}

// ---------------- dual GEMM: P = H@Wrel, Rb = H@Wroot + b (f32x2 SIMT, R9) ----------------
#define WT_STRIDE 130           // Wt[256][130] transposed (f-major, k contiguous)
#define AS_STRIDE 132           // As[64][132]
#define GEMM_SMEM ((256*WT_STRIDE + 64*AS_STRIDE + 128)*4)

__global__ void __launch_bounds__(256) k_gemm(int layer,
                         const float* __restrict__ Wrel, const float* __restrict__ Wroot,
                         const float* __restrict__ bias){
    extern __shared__ float sm[];
    float* Wt = sm;                         // 256*130
    float* As = sm + 256*WT_STRIDE;         // 64*132
    float* bs = As + 64*AS_STRIDE;          // 128
    const float* __restrict__ Hin = (layer == 2) ? g_HA : g_HB;
    const int t = threadIdx.x;

    for (int i = t; i < 256*128; i += 256){
        int f = i >> 7, k = i & 127;
        float v = (f < 128) ? Wrel[k*128 + f] : Wroot[k*128 + (f-128)];
        Wt[f*WT_STRIDE + k] = v;
    }
    if (t < 128) bs[t] = bias[t];
    __syncthreads();

    const int r = t >> 5;      // 0..7  -> 8 rows each
    const int c = t & 31;      // 0..31 -> cols f = c + 32*j

    for (int tile = blockIdx.x; tile < GT; tile += gridDim.x){
        #pragma unroll
        for (int i = 0; i < 8; i++){
            int lin = t + 256*i;                 // 0..2047
            int row = lin >> 5;
            int kc  = (lin & 31) << 2;
            float4 v = *(const float4*)(Hin + (size_t)(tile*64 + row)*128 + kc);
            *(float4*)(As + row*AS_STRIDE + kc) = v;
        }
        __syncthreads();

        ull acc[8][8];
        #pragma unroll
        for (int i = 0; i < 8; i++)
            #pragma unroll
            for (int j = 0; j < 8; j++) acc[i][j] = 0ULL;

        #pragma unroll 4
        for (int k = 0; k < 128; k += 2){
            ull a[8], b[8];
            #pragma unroll
            for (int i = 0; i < 8; i++)
                a[i] = *(const ull*)(As + (r*8 + i)*AS_STRIDE + k);
            #pragma unroll
            for (int j = 0; j < 8; j++)
                b[j] = *(const ull*)(Wt + (c + 32*j)*WT_STRIDE + k);
            #pragma unroll
            for (int i = 0; i < 8; i++)
                #pragma unroll
                for (int j = 0; j < 8; j++)
                    fma2(acc[i][j], a[i], b[j]);
        }

        #pragma unroll
        for (int i = 0; i < 8; i++){
            size_t node = (size_t)tile*64 + r*8 + i;
            #pragma unroll
            for (int j = 0; j < 8; j++){
                float2 p = unpack2(acc[i][j]);
                float v = p.x + p.y;
                int f = c + 32*j;
                if (f < 128) g_P [node*128 + f]       = v;
                else         g_Rb[node*128 + (f-128)] = v + bs[f-128];
            }
        }
        __syncthreads();
    }
}

// ---------------- conv-apply (sparse): H_out = relu(sum_{j->n} P_j + Rb_n) ----------------
#define PST 130
__global__ void __launch_bounds__(544) k_conv(int layer){
    __shared__ float Ps[NP*PST];
    const int g = blockIdx.x, t = threadIdx.x;
    float* __restrict__ Hout = (layer == 2) ? g_HB : g_HA;

    const float* Pg = g_P + (size_t)g*NP*FH;
    for (int i = t; i < NP*FH; i += 544){
        int row = i >> 7, col = i & 127;
        Ps[row*PST + col] = Pg[i];
    }
    __syncthreads();

    const int n  = t >> 3;     // 0..67
    const int cg = t & 7;      // 0..7 -> pair cols cg + 8u
    const int off = g_off[g*NP + n];
    const int cnt = g_cnt[g*NP + n];

    const float* rb = g_Rb + ((size_t)g*NP + n)*FH;
    ull acc[8];
    #pragma unroll
    for (int u = 0; u < 8; u++) acc[u] = *(const ull*)(rb + 2*(cg + 8*u));

    const ull one = dup2(1.0f);
    for (int e = 0; e < cnt; e++){
        const float* pr = Ps + ((int)g_srcs[off+e])*PST;
        #pragma unroll
        for (int u = 0; u < 8; u++){
            ull pv = *(const ull*)(pr + 2*(cg + 8*u));
            fma2(acc[u], one, pv);
        }
    }
    float* ho = Hout + ((size_t)g*NP + n)*FH;
    #pragma unroll
    for (int u = 0; u < 8; u++){
        float2 v = unpack2(acc[u]);
        v.x = fmaxf(v.x, 0.0f); v.y = fmaxf(v.y, 0.0f);
        *(float2*)(ho + 2*(cg + 8*u)) = v;
    }
}

// ---------------- pool: softmax(s) einsum, maxpool(1,8), fc ----------------
__global__ void __launch_bounds__(512) k_pool(const float* __restrict__ s_in,
                       const float* __restrict__ fcw, const float* __restrict__ fcb,
                       float* __restrict__ out){
    __shared__ float Hs[NP*FH];     // 34816B
    __shared__ float ssm[NP*NC];
    __shared__ float xp[NC*FH];
    __shared__ float red[128];
    const int g = blockIdx.x, t = threadIdx.x;

    const float* Hg = g_HA + (size_t)g*NP*FH;
    for (int i = t; i < NP*FH; i += 512) Hs[i] = Hg[i];

    if (t < NP){
        float v[NC]; float m = -1e30f;
        #pragma unroll
        for (int k = 0; k < NC; k++){ v[k] = s_in[((size_t)g*NP + t)*NC + k]; m = fmaxf(m, v[k]); }
        float sum = 0.0f;
        #pragma unroll
        for (int k = 0; k < NC; k++){ v[k] = expf(v[k]-m); sum += v[k]; }
        float inv = 1.0f/sum;
        #pragma unroll
        for (int k = 0; k < NC; k++) ssm[t*NC+k] = v[k]*inv;
    }
    __syncthreads();

    for (int idx = t; idx < NC*FH; idx += 512){
        int c = idx >> 7, f = idx & 127;
        float acc = 0.0f;
        #pragma unroll 4
        for (int n = 0; n < NP; n++) acc += ssm[n*NC+c] * Hs[n*FH + f];
        xp[c*FH + f] = acc;
    }
    __syncthreads();

    if (t < 128){
        int c = t >> 4, j = t & 15;
        float m = xp[c*FH + j*8];
        #pragma unroll
        for (int u = 1; u < 8; u++) m = fmaxf(m, xp[c*FH + j*8 + u]);
        red[t] = m * fcw[t];
    }
    __syncthreads();
    if (t < 64) red[t] += red[t+64];
    __syncthreads();
    if (t < 32){
        float v = red[t] + red[t+32];
        #pragma unroll
        for (int o = 16; o; o >>= 1) v += __shfl_down_sync(0xffffffffu, v, o);
        if (t == 0) out[g] = v + fcb[0];
    }
}

// ---------------- launch ----------------
extern "C" void kernel_launch(void* const* d_in, const int* in_sizes, int n_in,
                              void* d_out, int out_size){
    const float* x    = (const float*)d_in[0];
    const int*   ei   = (const int*)  d_in[1];
    // d_in[2] = adj : unused (pool losses are discarded in reference)
    const float* s_in = (const float*)d_in[3];
    const float* Wro1 = (const float*)d_in[4];
    const float* Wre1 = (const float*)d_in[5];
    const float* b1   = (const float*)d_in[6];
    const float* Wro2 = (const float*)d_in[7];
    const float* Wre2 = (const float*)d_in[8];
    const float* b2   = (const float*)d_in[9];
    const float* Wro3 = (const float*)d_in[10];
    const float* Wre3 = (const float*)d_in[11];
    const float* b3   = (const float*)d_in[12];
    const float* fcw  = (const float*)d_in[13];
    const float* fcb  = (const float*)d_in[14];
    float* out = (float*)d_out;
    (void)in_sizes; (void)n_in; (void)out_size;

    cudaFuncSetAttribute(k_gemm, cudaFuncAttributeMaxDynamicSharedMemorySize, GEMM_SMEM);

    k_detect<<<1, 256>>>(ei);
    k_zcnt<<<(NN+255)/256, 256>>>();
    k_count<<<EE/256, 256>>>(ei);
    k_offs<<<BB, 32>>>();
    k_scatter<<<EE/256, 256>>>(ei);
    k_sortsrc<<<(NN+255)/256, 256>>>();

    k_layer1<<<BB, 256>>>(x, Wre1, Wro1, b1);                 // -> g_HA

    k_gemm<<<296, 256, GEMM_SMEM>>>(2, Wre2, Wro2, b2);       // g_HA -> g_P, g_Rb
    k_conv<<<BB, 544>>>(2);                                   // -> g_HB

    k_gemm<<<296, 256, GEMM_SMEM>>>(3, Wre3, Wro3, b3);       // g_HB -> g_P, g_Rb
    k_conv<<<BB, 544>>>(3);                                   // -> g_HA

    k_pool<<<BB, 512>>>(s_in, fcw, fcb, out);
}